// round 14
// baseline (speedup 1.0000x reference)
#include <cuda_runtime.h>
#include <cuda_bf16.h>
#include <math.h>

// Problem constants
#define B_IMG   32
#define HW      56
#define CCH     192
#define NHEAD   6
#define HDIM    32
#define NTOK    49
#define NWIN    64
#define BWIN    2048
#define TOK     100352
#define SHIFT_  3
#define QSCALE  0.17677669529663687f

#define BM_SZ   3840
#define NKB     12
#define AT16    12288
#define QT16    1024
#define KT16    896
#define VT16    1024
#define NPTILE  1024      // padded-token tiles (131072 rows / 128)

__device__ __forceinline__ int aw_idx(int rr, int p) {
    return (((rr >> 4) * NKB + (p >> 3)) << 7)
         + (((rr & 7) * 4 + (p & 3)) << 2)
         + ((rr >> 3) & 1) + (((p >> 2) & 1) << 1);
}

__device__ __forceinline__ unsigned pk(float lo, float hi) {
    unsigned r;
    asm("cvt.rn.bf16x2.f32 %0, %1, %2;" : "=r"(r) : "f"(hi), "f"(lo));
    return r;
}

// ---------------- scratch ----------------
__device__ unsigned g_xa [ (size_t)NPTILE * AT16 ];   // LN out, padded window-token space
__device__ unsigned g_ca [ (size_t)NPTILE * AT16 ];   // ctx, padded window-token space
__device__ unsigned g_ya [ (size_t)784 * AT16 ];      // proj out, real-token space
__device__ unsigned g_q  [ (size_t)BWIN * NHEAD * QT16 ];
__device__ unsigned g_k  [ (size_t)BWIN * NHEAD * KT16 ];
__device__ unsigned g_v  [ (size_t)BWIN * NHEAD * VT16 ];
__device__ float    g_bm [ (size_t)NHEAD * NWIN * BM_SZ ];
__device__ unsigned g_wq [ 72 * NKB * 64 ];
__device__ unsigned g_wp [ 24 * NKB * 64 ];
__device__ unsigned g_wl [ 24 * NKB * 64 ];

// ---------------- K0: combined bias+mask table ----------------
__global__ void bias2_kernel(const float* __restrict__ table, const int* __restrict__ idx,
                             const float* __restrict__ mask)
{
    int i = blockIdx.x * blockDim.x + threadIdx.x;
    if (i >= NHEAD * NWIN * BM_SZ) return;
    int c  = i % 60;
    int r  = (i / 60) & 63;
    int wi = (i / BM_SZ) & 63;
    int h  = i / (BM_SZ * NWIN);
    float v = -1e9f;
    if (r < NTOK && c < NTOK)
        v = table[idx[r * NTOK + c] * NHEAD + h] + mask[(wi * NTOK + r) * NTOK + c];
    g_bm[i] = v;
}

// ---------------- K0c: weight pre-swizzle -> bf16 B-fragment ----------------
__global__ void wswz_kernel(const float* __restrict__ wq, const float* __restrict__ wp,
                            const float* __restrict__ wl)
{
    int i = blockIdx.x * blockDim.x + threadIdx.x;
    int total = (576 + 192 + 192) * 96;
    if (i >= total) return;
    const float* src; unsigned* dst; int n;
    if (i < 576 * 96)      { src = wq; dst = g_wq; n = i; }
    else if (i < 768 * 96) { src = wp; dst = g_wp; n = i - 576 * 96; }
    else                   { src = wl; dst = g_wl; n = i - 768 * 96; }
    int row = n / 96, p = n % 96;
    int w = (((row >> 3) * NKB + (p >> 3)) << 6)
          + (((row & 7) * 4 + (p & 3)) << 1) + ((p >> 2) & 1);
    dst[w] = pk(src[row * 192 + 2 * p], src[row * 192 + 2 * p + 1]);
}

// ---------------- K1: LN + shift + window partition -> padded bf16 A-frag ---
__global__ void __launch_bounds__(256) ln_kernel(const float* __restrict__ x,
                                                 const float* __restrict__ g,
                                                 const float* __restrict__ b)
{
    int wid  = (blockIdx.x * blockDim.x + threadIdx.x) >> 5;
    int lane = threadIdx.x & 31;
    if (wid >= TOK) return;

    int w  = wid / NTOK, n = wid % NTOK;
    int bb = w >> 6, wi = w & 63;
    int wh = wi >> 3, ww = wi & 7;
    int ii = n / 7,  jj = n % 7;
    int hh = (wh * 7 + ii + SHIFT_) % HW;
    int w2 = (ww * 7 + jj + SHIFT_) % HW;
    const float2* src = (const float2*)(x + ((size_t)bb * (HW * HW) + hh * HW + w2) * CCH);

    float2 v[3];
    float s = 0.f, s2 = 0.f;
#pragma unroll
    for (int u = 0; u < 3; u++) {
        v[u] = src[lane + u * 32];
        s  += v[u].x + v[u].y;
        s2 += v[u].x * v[u].x + v[u].y * v[u].y;
    }
#pragma unroll
    for (int off = 16; off; off >>= 1) {
        s  += __shfl_xor_sync(0xFFFFFFFFu, s,  off);
        s2 += __shfl_xor_sync(0xFFFFFFFFu, s2, off);
    }
    float mu  = s * (1.f / CCH);
    float var = s2 * (1.f / CCH) - mu * mu;
    float inv = rsqrtf(var + 1e-5f);

    int P = w * 64 + n;                      // padded window-token index
    unsigned* dst = g_xa + (size_t)(P >> 7) * AT16;
    int rr = P & 127;
    const float2* g2 = (const float2*)g;
    const float2* b2 = (const float2*)b;
#pragma unroll
    for (int u = 0; u < 3; u++) {
        int p = lane + u * 32;
        float2 gg = g2[p], bb2 = b2[p];
        float lo = (v[u].x - mu) * inv * gg.x + bb2.x;
        float hi = (v[u].y - mu) * inv * gg.y + bb2.y;
        dst[aw_idx(rr, p)] = pk(lo, hi);
    }
}

__device__ __forceinline__ void mma_bf16(float* d, const unsigned* a, const unsigned* b) {
    asm volatile(
        "mma.sync.aligned.m16n8k16.row.col.f32.bf16.bf16.f32 "
        "{%0,%1,%2,%3}, {%4,%5,%6,%7}, {%8,%9}, {%0,%1,%2,%3};\n"
        : "+f"(d[0]), "+f"(d[1]), "+f"(d[2]), "+f"(d[3])
        : "r"(a[0]), "r"(a[1]), "r"(a[2]), "r"(a[3]), "r"(b[0]), "r"(b[1]));
}

// ---------------- GEMM: bf16, no smem, coalesced epilogues ------------------
template<int EPI>
__global__ void __launch_bounds__(256) gemm_kernel(const float* __restrict__ bias,
                                                   const float* __restrict__ resid,
                                                   float* __restrict__ out)
{
    const unsigned* A   = (EPI == 0) ? g_xa : (EPI == 1 ? g_ca : g_ya);
    const unsigned* Wsw = (EPI == 0) ? g_wq : (EPI == 1 ? g_wp : g_wl);

    int tid  = threadIdx.x;
    int lane = tid & 31, wid = tid >> 5;
    int wm = wid >> 1, wn = wid & 1;
    int gid = lane >> 2, qid = lane & 3;
    int row0 = blockIdx.y * 128;
    int col0 = blockIdx.x * 64;

    const unsigned* Ab = A + (size_t)blockIdx.y * AT16 + (wm * 2 * NKB) * 128 + lane * 4;
    const unsigned* Bb = Wsw + (size_t)(blockIdx.x * 8 + wn * 4) * (NKB * 64) + lane * 2;

    float acc[2][4][4];
#pragma unroll
    for (int i = 0; i < 2; i++)
#pragma unroll
        for (int j = 0; j < 4; j++)
#pragma unroll
            for (int r = 0; r < 4; r++) acc[i][j][r] = 0.f;

#pragma unroll
    for (int kg = 0; kg < NKB; kg++) {
        uint4 af0 = *(const uint4*)(Ab + kg * 128);
        uint4 af1 = *(const uint4*)(Ab + NKB * 128 + kg * 128);
        uint2 bf[4];
#pragma unroll
        for (int ni = 0; ni < 4; ni++)
            bf[ni] = *(const uint2*)(Bb + ni * (NKB * 64) + kg * 64);
#pragma unroll
        for (int ni = 0; ni < 4; ni++) {
            mma_bf16(acc[0][ni], (const unsigned*)&af0, (const unsigned*)&bf[ni]);
            mma_bf16(acc[1][ni], (const unsigned*)&af1, (const unsigned*)&bf[ni]);
        }
    }

    if (EPI == 0) {
        int cbase = col0 + wn * 32;          // one head's 32 columns
        int m  = cbase / CCH;
        int hd = (cbase % CCH) >> 5;
        float2 bia[4];
#pragma unroll
        for (int ni = 0; ni < 4; ni++)
            bia[ni] = *(const float2*)&bias[cbase + ni * 8 + qid * 2];

        if (m == 0) {            // Q: 2 x STG.128 per mi, fully coalesced
#pragma unroll
            for (int mi = 0; mi < 2; mi++) {
                int rb = row0 + wm * 32 + mi * 16;
                int w = rb >> 6, n16 = rb & 63;
                unsigned* qp = g_q + (size_t)(w * NHEAD + hd) * QT16
                             + ((n16 >> 4) * 2) * 128 + gid * 16 + qid * 4;
#pragma unroll
                for (int kb = 0; kb < 2; kb++) {
                    int n0 = 2 * kb, n1 = 2 * kb + 1;
                    uint4 st;
                    st.x = pk((acc[mi][n0][0] + bia[n0].x) * QSCALE, (acc[mi][n0][1] + bia[n0].y) * QSCALE);
                    st.y = pk((acc[mi][n0][2] + bia[n0].x) * QSCALE, (acc[mi][n0][3] + bia[n0].y) * QSCALE);
                    st.z = pk((acc[mi][n1][0] + bia[n1].x) * QSCALE, (acc[mi][n1][1] + bia[n1].y) * QSCALE);
                    st.w = pk((acc[mi][n1][2] + bia[n1].x) * QSCALE, (acc[mi][n1][3] + bia[n1].y) * QSCALE);
                    *(uint4*)(qp + kb * 128) = st;
                }
            }
        } else if (m == 1) {     // K: coalesced STG.64s (skip keys >= 56)
#pragma unroll
            for (int mi = 0; mi < 2; mi++) {
                int rb = row0 + wm * 32 + mi * 16;
                int w = rb >> 6, n16 = rb & 63;
                unsigned* kp_ = g_k + (size_t)(w * NHEAD + hd) * KT16 + gid * 8 + qid * 2;
                int bb0 = (n16 >> 3);        // {0,2,4,6}
#pragma unroll
                for (int half = 0; half < 2; half++) {
                    if (n16 == 48 && half == 1) continue;
#pragma unroll
                    for (int kb = 0; kb < 2; kb++) {
                        int n0 = 2 * kb, n1 = 2 * kb + 1;
                        int blk = (bb0 + half) * 2 + kb;
                        uint2 st;
                        st.x = pk(acc[mi][n0][2 * half] + bia[n0].x, acc[mi][n0][2 * half + 1] + bia[n0].y);
                        st.y = pk(acc[mi][n1][2 * half] + bia[n1].x, acc[mi][n1][2 * half + 1] + bia[n1].y);
                        *(uint2*)(kp_ + blk * 64) = st;
                    }
                }
            }
        } else {                 // V: pair-exchange shuffle, coalesced STG.64s
            int e = gid & 1;
#pragma unroll
            for (int mi = 0; mi < 2; mi++) {
                int rb = row0 + wm * 32 + mi * 16;
                int w = rb >> 6, n16 = rb & 63;
                int K4 = n16 >> 4;
                unsigned* vp = g_v + (size_t)(w * NHEAD + hd) * VT16
                             + K4 * 64 + qid * 16 + e * 8 + ((gid >> 1) & 3) * 2;
#pragma unroll
                for (int ni = 0; ni < 4; ni++) {
                    float v00 = acc[mi][ni][0] + bia[ni].x;   // (h0, e0)
                    float v01 = acc[mi][ni][2] + bia[ni].x;   // (h1, e0)
                    float v10 = acc[mi][ni][1] + bia[ni].y;   // (h0, e1)
                    float v11 = acc[mi][ni][3] + bia[ni].y;   // (h1, e1)
                    float r00 = __shfl_xor_sync(0xFFFFFFFFu, v00, 4);
                    float r01 = __shfl_xor_sync(0xFFFFFFFFu, v01, 4);
                    float r10 = __shfl_xor_sync(0xFFFFFFFFu, v10, 4);
                    float r11 = __shfl_xor_sync(0xFFFFFFFFu, v11, 4);
                    uint2 st;
                    if (e == 0) { st.x = pk(v00, r00); st.y = pk(v01, r01); }
                    else        { st.x = pk(r10, v10); st.y = pk(r11, v11); }
                    *(uint2*)(vp + ni * 256) = st;
                }
            }
        }
    } else if (EPI == 1) {
#pragma unroll
        for (int mi = 0; mi < 2; mi++) {
#pragma unroll
            for (int half = 0; half < 2; half++) {
                int R = row0 + wm * 32 + mi * 16 + gid + half * 8;
                int w = R >> 6, n = R & 63;
                if (n < NTOK) {
                    int bb = w >> 6, wi = w & 63;
                    int wh = wi >> 3, ww = wi & 7;
                    int ii = n / 7, jj = n % 7;
                    int hh = (wh * 7 + ii + SHIFT_) % HW;
                    int w2 = (ww * 7 + jj + SHIFT_) % HW;
                    int t  = bb * (HW * HW) + hh * HW + w2;
                    unsigned* dst = g_ya + (size_t)(t >> 7) * AT16;
                    int rr = t & 127;
#pragma unroll
                    for (int ni = 0; ni < 4; ni++) {
                        int c0 = col0 + wn * 32 + ni * 8 + qid * 2;
                        float lo = acc[mi][ni][half * 2 + 0] + bias[c0];
                        float hi = acc[mi][ni][half * 2 + 1] + bias[c0 + 1];
                        dst[aw_idx(rr, c0 >> 1)] = pk(lo, hi);
                    }
                }
            }
        }
    } else {
#pragma unroll
        for (int mi = 0; mi < 2; mi++) {
#pragma unroll
            for (int half = 0; half < 2; half++) {
                int r = row0 + wm * 32 + mi * 16 + gid + half * 8;
                const float* rs = resid + (size_t)r * CCH;
                float* dp = out + (size_t)r * CCH;
#pragma unroll
                for (int ni = 0; ni < 4; ni++) {
                    int c0 = col0 + wn * 32 + ni * 8 + qid * 2;
                    float v0 = acc[mi][ni][half * 2 + 0] + bias[c0];
                    float v1 = acc[mi][ni][half * 2 + 1] + bias[c0 + 1];
                    float g0 = 0.5f * v0 * (1.f + erff(v0 * 0.70710678118654752f));
                    float g1 = 0.5f * v1 * (1.f + erff(v1 * 0.70710678118654752f));
                    float2 rv = *(const float2*)&rs[c0];
                    float2 ov = make_float2(rv.x + g0, rv.y + g1);
                    *(float2*)&dp[c0] = ov;
                }
            }
        }
    }
}

// ---------------- K3: windowed attention, all-bf16, no smem -----------------
__global__ void __launch_bounds__(128) attn_kernel()
{
    int w = blockIdx.x, h = blockIdx.y;
    int tid = threadIdx.x;
    int lane = tid & 31, wrp = tid >> 5;
    int gid = lane >> 2, qid = lane & 3;

    size_t tb = (size_t)(w * NHEAD + h);
    const unsigned* __restrict__ qt = g_q + tb * QT16;
    const unsigned* __restrict__ kt = g_k + tb * KT16;
    const unsigned* __restrict__ vt = g_v + tb * VT16;
    const float* __restrict__ bmp = g_bm + ((size_t)h * NWIN + (w & 63)) * BM_SZ;

    int m0 = wrp * 16;

    float sacc[7][4];
#pragma unroll
    for (int nt = 0; nt < 7; nt++)
#pragma unroll
        for (int r = 0; r < 4; r++) sacc[nt][r] = 0.f;

    const unsigned* Ab = qt + (wrp * 2) * 128 + lane * 4;
#pragma unroll
    for (int kb = 0; kb < 2; kb++) {
        uint4 av = *(const uint4*)(Ab + kb * 128);
#pragma unroll
        for (int nt = 0; nt < 7; nt++) {
            uint2 bv = *(const uint2*)(kt + (nt * 2 + kb) * 64 + lane * 2);
            mma_bf16(sacc[nt], (const unsigned*)&av, (const unsigned*)&bv);
        }
    }

#pragma unroll
    for (int nt = 0; nt < 7; nt++) {
        float2 t0 = *(const float2*)&bmp[(m0 + gid) * 60 + nt * 8 + 2 * qid];
        float2 t1 = *(const float2*)&bmp[(m0 + gid + 8) * 60 + nt * 8 + 2 * qid];
        sacc[nt][0] += t0.x; sacc[nt][1] += t0.y;
        sacc[nt][2] += t1.x; sacc[nt][3] += t1.y;
    }

    float mx0 = -1e30f, mx1 = -1e30f;
#pragma unroll
    for (int nt = 0; nt < 7; nt++) {
        mx0 = fmaxf(mx0, fmaxf(sacc[nt][0], sacc[nt][1]));
        mx1 = fmaxf(mx1, fmaxf(sacc[nt][2], sacc[nt][3]));
    }
    mx0 = fmaxf(mx0, __shfl_xor_sync(0xFFFFFFFFu, mx0, 1));
    mx0 = fmaxf(mx0, __shfl_xor_sync(0xFFFFFFFFu, mx0, 2));
    mx1 = fmaxf(mx1, __shfl_xor_sync(0xFFFFFFFFu, mx1, 1));
    mx1 = fmaxf(mx1, __shfl_xor_sync(0xFFFFFFFFu, mx1, 2));

    float sum0 = 0.f, sum1 = 0.f;
#pragma unroll
    for (int nt = 0; nt < 7; nt++) {
        sacc[nt][0] = __expf(sacc[nt][0] - mx0);
        sacc[nt][1] = __expf(sacc[nt][1] - mx0);
        sacc[nt][2] = __expf(sacc[nt][2] - mx1);
        sacc[nt][3] = __expf(sacc[nt][3] - mx1);
        sum0 += sacc[nt][0] + sacc[nt][1];
        sum1 += sacc[nt][2] + sacc[nt][3];
    }
    sum0 += __shfl_xor_sync(0xFFFFFFFFu, sum0, 1);
    sum0 += __shfl_xor_sync(0xFFFFFFFFu, sum0, 2);
    sum1 += __shfl_xor_sync(0xFFFFFFFFu, sum1, 1);
    sum1 += __shfl_xor_sync(0xFFFFFFFFu, sum1, 2);
    float inv0 = 1.f / sum0, inv1 = 1.f / sum1;
#pragma unroll
    for (int nt = 0; nt < 7; nt++) {
        sacc[nt][0] *= inv0; sacc[nt][1] *= inv0;
        sacc[nt][2] *= inv1; sacc[nt][3] *= inv1;
    }

    float o[4][4];
#pragma unroll
    for (int dt = 0; dt < 4; dt++)
#pragma unroll
        for (int r = 0; r < 4; r++) o[dt][r] = 0.f;

#pragma unroll
    for (int kb = 0; kb < 4; kb++) {
        unsigned a[4];
        int n0 = 2 * kb, n1 = 2 * kb + 1;
        a[0] = pk(sacc[n0][0], sacc[n0][1]);
        a[1] = pk(sacc[n0][2], sacc[n0][3]);
        if (n1 < 7) {
            a[2] = pk(sacc[n1][0], sacc[n1][1]);
            a[3] = pk(sacc[n1][2], sacc[n1][3]);
        } else { a[2] = 0u; a[3] = 0u; }
#pragma unroll
        for (int dt = 0; dt < 4; dt++) {
            uint2 bv = *(const uint2*)(vt + (dt * 4 + kb) * 64 + lane * 2);
            mma_bf16(o[dt], a, (const unsigned*)&bv);
        }
    }

    // ---- write ctx into padded window-token space ----
    int r0 = m0 + gid, r1 = r0 + 8;
    int R0 = w * 64 + r0, R1 = w * 64 + r1;
    unsigned* d0 = g_ca + (size_t)(R0 >> 7) * AT16;
    unsigned* d1 = g_ca + (size_t)(R1 >> 7) * AT16;
    int rr0 = R0 & 127, rr1 = R1 & 127;
#pragma unroll
    for (int dt = 0; dt < 4; dt++) {
        int p = (h * HDIM + dt * 8 + 2 * qid) >> 1;
        if (r0 < NTOK) d0[aw_idx(rr0, p)] = pk(o[dt][0], o[dt][1]);
        if (r1 < NTOK) d1[aw_idx(rr1, p)] = pk(o[dt][2], o[dt][3]);
    }
}

// ---------------- launch ----------------
extern "C" void kernel_launch(void* const* d_in, const int* in_sizes, int n_in,
                              void* d_out, int out_size)
{
    const float* inputs = (const float*)d_in[0];
    const float* amask  = (const float*)d_in[1];
    const float* n1g    = (const float*)d_in[2];
    const float* n1b    = (const float*)d_in[3];
    const float* qkvw   = (const float*)d_in[4];
    const float* qkvb   = (const float*)d_in[5];
    const float* rpt    = (const float*)d_in[6];
    const int*   rpi    = (const int*)d_in[7];
    const float* pw     = (const float*)d_in[8];
    const float* pb     = (const float*)d_in[9];
    const float* lw     = (const float*)d_in[10];
    const float* lb     = (const float*)d_in[11];
    float* out = (float*)d_out;

    bias2_kernel<<<(NHEAD * NWIN * BM_SZ + 255) / 256, 256>>>(rpt, rpi, amask);
    wswz_kernel<<<((576 + 192 + 192) * 96 + 255) / 256, 256>>>(qkvw, pw, lw);
    ln_kernel<<<TOK / 8, 256>>>(inputs, n1g, n1b);
    gemm_kernel<0><<<dim3(9, NPTILE), 256>>>(qkvb, nullptr, nullptr);
    attn_kernel<<<dim3(BWIN, NHEAD), 128>>>();
    gemm_kernel<1><<<dim3(3, NPTILE), 256>>>(pb, nullptr, nullptr);
    gemm_kernel<2><<<dim3(3, 784), 256>>>(lb, inputs, out);
}

// round 15
// speedup vs baseline: 1.4329x; 1.4329x over previous
#include <cuda_runtime.h>
#include <cuda_bf16.h>
#include <math.h>

// Problem constants
#define B_IMG   32
#define HW      56
#define CCH     192
#define NHEAD   6
#define HDIM    32
#define NTOK    49
#define NWIN    64
#define BWIN    2048
#define TOK     100352
#define SHIFT_  3
#define QSCALE  0.17677669529663687f

#define BM_SZ   3840
#define NKB     12
#define AT16    12288
#define QT16    1024
#define KT16    896
#define VT16    1024

__device__ __forceinline__ int aw_idx(int rr, int p) {
    return (((rr >> 4) * NKB + (p >> 3)) << 7)
         + (((rr & 7) * 4 + (p & 3)) << 2)
         + ((rr >> 3) & 1) + (((p >> 2) & 1) << 1);
}

__device__ __forceinline__ unsigned pk(float lo, float hi) {
    unsigned r;
    asm("cvt.rn.bf16x2.f32 %0, %1, %2;" : "=r"(r) : "f"(hi), "f"(lo));
    return r;
}

__device__ __forceinline__ void cpa16(unsigned sa, const unsigned* g) {
    asm volatile("cp.async.cg.shared.global [%0], [%1], 16;" :: "r"(sa), "l"(g));
}

// ---------------- scratch ----------------
__device__ unsigned g_xa [ (size_t)784 * AT16 ];
__device__ unsigned g_ca [ (size_t)784 * AT16 ];
__device__ unsigned g_ya [ (size_t)784 * AT16 ];
__device__ unsigned g_q  [ (size_t)BWIN * NHEAD * QT16 ];
__device__ unsigned g_k  [ (size_t)BWIN * NHEAD * KT16 ];
__device__ unsigned g_v  [ (size_t)BWIN * NHEAD * VT16 ];
__device__ float    g_bm [ (size_t)NHEAD * NWIN * BM_SZ ];
__device__ unsigned g_wq [ 72 * NKB * 64 ];
__device__ unsigned g_wp [ 24 * NKB * 64 ];
__device__ unsigned g_wl [ 24 * NKB * 64 ];

// ---------------- K0: combined bias+mask table ----------------
__global__ void bias2_kernel(const float* __restrict__ table, const int* __restrict__ idx,
                             const float* __restrict__ mask)
{
    int i = blockIdx.x * blockDim.x + threadIdx.x;
    if (i >= NHEAD * NWIN * BM_SZ) return;
    int c  = i % 60;
    int r  = (i / 60) & 63;
    int wi = (i / BM_SZ) & 63;
    int h  = i / (BM_SZ * NWIN);
    float v = -1e9f;
    if (r < NTOK && c < NTOK)
        v = table[idx[r * NTOK + c] * NHEAD + h] + mask[(wi * NTOK + r) * NTOK + c];
    g_bm[i] = v;
}

// ---------------- K0c: weight pre-swizzle -> bf16 B-fragment ----------------
__global__ void wswz_kernel(const float* __restrict__ wq, const float* __restrict__ wp,
                            const float* __restrict__ wl)
{
    int i = blockIdx.x * blockDim.x + threadIdx.x;
    int total = (576 + 192 + 192) * 96;
    if (i >= total) return;
    const float* src; unsigned* dst; int n;
    if (i < 576 * 96)      { src = wq; dst = g_wq; n = i; }
    else if (i < 768 * 96) { src = wp; dst = g_wp; n = i - 576 * 96; }
    else                   { src = wl; dst = g_wl; n = i - 768 * 96; }
    int row = n / 96, p = n % 96;
    int w = (((row >> 3) * NKB + (p >> 3)) << 6)
          + (((row & 7) * 4 + (p & 3)) << 1) + ((p >> 2) & 1);
    dst[w] = pk(src[row * 192 + 2 * p], src[row * 192 + 2 * p + 1]);
}

// ---------------- K1: LN + shift + window partition -> bf16 A-frag ----------
__global__ void __launch_bounds__(256) ln_kernel(const float* __restrict__ x,
                                                 const float* __restrict__ g,
                                                 const float* __restrict__ b)
{
    int wid  = (blockIdx.x * blockDim.x + threadIdx.x) >> 5;
    int lane = threadIdx.x & 31;
    if (wid >= TOK) return;

    int w  = wid / NTOK, n = wid % NTOK;
    int bb = w >> 6, wi = w & 63;
    int wh = wi >> 3, ww = wi & 7;
    int ii = n / 7,  jj = n % 7;
    int hh = (wh * 7 + ii + SHIFT_) % HW;
    int w2 = (ww * 7 + jj + SHIFT_) % HW;
    const float2* src = (const float2*)(x + ((size_t)bb * (HW * HW) + hh * HW + w2) * CCH);

    float2 v[3];
    float s = 0.f, s2 = 0.f;
#pragma unroll
    for (int u = 0; u < 3; u++) {
        v[u] = src[lane + u * 32];
        s  += v[u].x + v[u].y;
        s2 += v[u].x * v[u].x + v[u].y * v[u].y;
    }
#pragma unroll
    for (int off = 16; off; off >>= 1) {
        s  += __shfl_xor_sync(0xFFFFFFFFu, s,  off);
        s2 += __shfl_xor_sync(0xFFFFFFFFu, s2, off);
    }
    float mu  = s * (1.f / CCH);
    float var = s2 * (1.f / CCH) - mu * mu;
    float inv = rsqrtf(var + 1e-5f);

    unsigned* dst = g_xa + (size_t)(wid >> 7) * AT16;
    int rr = wid & 127;
    const float2* g2 = (const float2*)g;
    const float2* b2 = (const float2*)b;
#pragma unroll
    for (int u = 0; u < 3; u++) {
        int p = lane + u * 32;
        float2 gg = g2[p], bb2 = b2[p];
        float lo = (v[u].x - mu) * inv * gg.x + bb2.x;
        float hi = (v[u].y - mu) * inv * gg.y + bb2.y;
        dst[aw_idx(rr, p)] = pk(lo, hi);
    }
}

__device__ __forceinline__ void mma_bf16(float* d, const unsigned* a, const unsigned* b) {
    asm volatile(
        "mma.sync.aligned.m16n8k16.row.col.f32.bf16.bf16.f32 "
        "{%0,%1,%2,%3}, {%4,%5,%6,%7}, {%8,%9}, {%0,%1,%2,%3};\n"
        : "+f"(d[0]), "+f"(d[1]), "+f"(d[2]), "+f"(d[3])
        : "r"(a[0]), "r"(a[1]), "r"(a[2]), "r"(a[3]), "r"(b[0]), "r"(b[1]));
}

// ---------------- GEMM: bf16, cp.async 4-stage pipeline ---------------------
template<int EPI>
__global__ void __launch_bounds__(256) gemm_kernel(const float* __restrict__ bias,
                                                   const float* __restrict__ resid,
                                                   float* __restrict__ out)
{
    const unsigned* A   = (EPI == 0) ? g_xa : (EPI == 1 ? g_ca : g_ya);
    const unsigned* Wsw = (EPI == 0) ? g_wq : (EPI == 1 ? g_wp : g_wl);

    __shared__ __align__(16) unsigned sA[4][1024];   // 4 KB / stage
    __shared__ __align__(16) unsigned sB[4][512];    // 2 KB / stage

    int tid  = threadIdx.x;
    int lane = tid & 31, wid = tid >> 5;
    int wm = wid >> 1, wn = wid & 1;
    int gid = lane >> 2, qid = lane & 3;
    int row0 = blockIdx.y * 128;
    int col0 = blockIdx.x * 64;

    // per-thread copy source/dest
    const unsigned* As = A + (size_t)blockIdx.y * AT16 + ((tid >> 5) * NKB) * 128 + (tid & 31) * 4;
    const unsigned* Bs = Wsw + (size_t)(blockIdx.x * 8 + ((tid >> 4) & 7)) * (NKB * 64) + (tid & 15) * 4;
    unsigned dA = (unsigned)__cvta_generic_to_shared(sA) + tid * 16;
    unsigned dB = (unsigned)__cvta_generic_to_shared(sB) + tid * 16;

    float acc[2][4][4];
#pragma unroll
    for (int i = 0; i < 2; i++)
#pragma unroll
        for (int j = 0; j < 4; j++)
#pragma unroll
            for (int r = 0; r < 4; r++) acc[i][j][r] = 0.f;

    // prologue: stages 0..2
#pragma unroll
    for (int s = 0; s < 3; s++) {
        cpa16(dA + s * 4096, As + s * 128);
        if (tid < 128) cpa16(dB + s * 2048, Bs + s * 64);
        asm volatile("cp.async.commit_group;");
    }

#pragma unroll
    for (int kg = 0; kg < NKB; kg++) {
        asm volatile("cp.async.wait_group 2;");
        __syncthreads();
        int jn = kg + 3;
        if (jn < NKB) {
            int s = jn & 3;
            cpa16(dA + s * 4096, As + jn * 128);
            if (tid < 128) cpa16(dB + s * 2048, Bs + jn * 64);
        }
        asm volatile("cp.async.commit_group;");

        int buf = kg & 3;
        uint4 af0 = *(const uint4*)&sA[buf][(wm * 2 + 0) * 128 + lane * 4];
        uint4 af1 = *(const uint4*)&sA[buf][(wm * 2 + 1) * 128 + lane * 4];
        uint2 bf[4];
#pragma unroll
        for (int ni = 0; ni < 4; ni++)
            bf[ni] = *(const uint2*)&sB[buf][(wn * 4 + ni) * 64 + lane * 2];
#pragma unroll
        for (int ni = 0; ni < 4; ni++) {
            mma_bf16(acc[0][ni], (const unsigned*)&af0, (const unsigned*)&bf[ni]);
            mma_bf16(acc[1][ni], (const unsigned*)&af1, (const unsigned*)&bf[ni]);
        }
    }

    if (EPI == 0) {
#pragma unroll
        for (int mi = 0; mi < 2; mi++) {
#pragma unroll
            for (int half = 0; half < 2; half++) {
                int r = row0 + wm * 32 + mi * 16 + gid + half * 8;
                int w = r / NTOK, n = r % NTOK;
#pragma unroll
                for (int ni = 0; ni < 4; ni++) {
                    int c0 = col0 + wn * 32 + ni * 8 + qid * 2;
                    float lo = acc[mi][ni][half * 2 + 0] + bias[c0];
                    float hi = acc[mi][ni][half * 2 + 1] + bias[c0 + 1];
                    int m = c0 / CCH, rem = c0 % CCH;
                    int hd = rem >> 5, d = rem & 31;
                    size_t tb = (size_t)(w * NHEAD + hd);
                    if (m == 0) {
                        int kp = d >> 1;
                        int word = ((n >> 4) * 2 + (kp >> 3)) * 128
                                 + ((n & 7) * 4 + (kp & 3)) * 4
                                 + ((n >> 3) & 1) + (((kp >> 2) & 1) << 1);
                        g_q[tb * QT16 + word] = pk(lo * QSCALE, hi * QSCALE);
                    } else if (m == 1) {
                        int kp = d >> 1;
                        int word = ((n >> 3) * 2 + (kp >> 3)) * 64
                                 + ((n & 7) * 4 + (kp & 3)) * 2 + ((kp >> 2) & 1);
                        g_k[tb * KT16 + word] = pk(lo, hi);
                    } else {
                        int kb = ((n >> 1) & 3), kh = ((n >> 3) & 1), blkk = (n >> 4);
                        int w0 = ((d >> 3) * 4 + blkk) * 64 + ((d & 7) * 4 + kb) * 2 + kh;
                        __nv_bfloat16* vv = (__nv_bfloat16*)g_v;
                        vv[(tb * VT16 + w0) * 2 + (n & 1)]     = __float2bfloat16(lo);
                        vv[(tb * VT16 + w0 + 8) * 2 + (n & 1)] = __float2bfloat16(hi);
                    }
                }
            }
        }
    } else if (EPI == 1) {
#pragma unroll
        for (int mi = 0; mi < 2; mi++) {
#pragma unroll
            for (int half = 0; half < 2; half++) {
                int r = row0 + wm * 32 + mi * 16 + gid + half * 8;
                int w = r / NTOK, n = r % NTOK;
                int bb = w >> 6, wi = w & 63;
                int wh = wi >> 3, ww = wi & 7;
                int ii = n / 7, jj = n % 7;
                int hh = (wh * 7 + ii + SHIFT_) % HW;
                int w2 = (ww * 7 + jj + SHIFT_) % HW;
                int t  = bb * (HW * HW) + hh * HW + w2;
                unsigned* dst = g_ya + (size_t)(t >> 7) * AT16;
                int rr = t & 127;
#pragma unroll
                for (int ni = 0; ni < 4; ni++) {
                    int c0 = col0 + wn * 32 + ni * 8 + qid * 2;
                    float lo = acc[mi][ni][half * 2 + 0] + bias[c0];
                    float hi = acc[mi][ni][half * 2 + 1] + bias[c0 + 1];
                    dst[aw_idx(rr, c0 >> 1)] = pk(lo, hi);
                }
            }
        }
    } else {
#pragma unroll
        for (int mi = 0; mi < 2; mi++) {
#pragma unroll
            for (int half = 0; half < 2; half++) {
                int r = row0 + wm * 32 + mi * 16 + gid + half * 8;
                const float* rs = resid + (size_t)r * CCH;
                float* dp = out + (size_t)r * CCH;
#pragma unroll
                for (int ni = 0; ni < 4; ni++) {
                    int c0 = col0 + wn * 32 + ni * 8 + qid * 2;
                    float v0 = acc[mi][ni][half * 2 + 0] + bias[c0];
                    float v1 = acc[mi][ni][half * 2 + 1] + bias[c0 + 1];
                    float g0 = 0.5f * v0 * (1.f + erff(v0 * 0.70710678118654752f));
                    float g1 = 0.5f * v1 * (1.f + erff(v1 * 0.70710678118654752f));
                    float2 rv = *(const float2*)&rs[c0];
                    float2 ov = make_float2(rv.x + g0, rv.y + g1);
                    *(float2*)&dp[c0] = ov;
                }
            }
        }
    }
}

// ---------------- K3: windowed attention, all-bf16, no smem -----------------
__global__ void __launch_bounds__(128) attn_kernel()
{
    int w = blockIdx.x, h = blockIdx.y;
    int tid = threadIdx.x;
    int lane = tid & 31, wrp = tid >> 5;
    int gid = lane >> 2, qid = lane & 3;

    size_t tb = (size_t)(w * NHEAD + h);
    const unsigned* __restrict__ qt = g_q + tb * QT16;
    const unsigned* __restrict__ kt = g_k + tb * KT16;
    const unsigned* __restrict__ vt = g_v + tb * VT16;
    const float* __restrict__ bmp = g_bm + ((size_t)h * NWIN + (w & 63)) * BM_SZ;

    int m0 = wrp * 16;

    float sacc[7][4];
#pragma unroll
    for (int nt = 0; nt < 7; nt++)
#pragma unroll
        for (int r = 0; r < 4; r++) sacc[nt][r] = 0.f;

    const unsigned* Ab = qt + (wrp * 2) * 128 + lane * 4;
#pragma unroll
    for (int kb = 0; kb < 2; kb++) {
        uint4 av = *(const uint4*)(Ab + kb * 128);
#pragma unroll
        for (int nt = 0; nt < 7; nt++) {
            uint2 bv = *(const uint2*)(kt + (nt * 2 + kb) * 64 + lane * 2);
            mma_bf16(sacc[nt], (const unsigned*)&av, (const unsigned*)&bv);
        }
    }

#pragma unroll
    for (int nt = 0; nt < 7; nt++) {
        float2 t0 = *(const float2*)&bmp[(m0 + gid) * 60 + nt * 8 + 2 * qid];
        float2 t1 = *(const float2*)&bmp[(m0 + gid + 8) * 60 + nt * 8 + 2 * qid];
        sacc[nt][0] += t0.x; sacc[nt][1] += t0.y;
        sacc[nt][2] += t1.x; sacc[nt][3] += t1.y;
    }

    float mx0 = -1e30f, mx1 = -1e30f;
#pragma unroll
    for (int nt = 0; nt < 7; nt++) {
        mx0 = fmaxf(mx0, fmaxf(sacc[nt][0], sacc[nt][1]));
        mx1 = fmaxf(mx1, fmaxf(sacc[nt][2], sacc[nt][3]));
    }
    mx0 = fmaxf(mx0, __shfl_xor_sync(0xFFFFFFFFu, mx0, 1));
    mx0 = fmaxf(mx0, __shfl_xor_sync(0xFFFFFFFFu, mx0, 2));
    mx1 = fmaxf(mx1, __shfl_xor_sync(0xFFFFFFFFu, mx1, 1));
    mx1 = fmaxf(mx1, __shfl_xor_sync(0xFFFFFFFFu, mx1, 2));

    float sum0 = 0.f, sum1 = 0.f;
#pragma unroll
    for (int nt = 0; nt < 7; nt++) {
        sacc[nt][0] = __expf(sacc[nt][0] - mx0);
        sacc[nt][1] = __expf(sacc[nt][1] - mx0);
        sacc[nt][2] = __expf(sacc[nt][2] - mx1);
        sacc[nt][3] = __expf(sacc[nt][3] - mx1);
        sum0 += sacc[nt][0] + sacc[nt][1];
        sum1 += sacc[nt][2] + sacc[nt][3];
    }
    sum0 += __shfl_xor_sync(0xFFFFFFFFu, sum0, 1);
    sum0 += __shfl_xor_sync(0xFFFFFFFFu, sum0, 2);
    sum1 += __shfl_xor_sync(0xFFFFFFFFu, sum1, 1);
    sum1 += __shfl_xor_sync(0xFFFFFFFFu, sum1, 2);
    float inv0 = 1.f / sum0, inv1 = 1.f / sum1;
#pragma unroll
    for (int nt = 0; nt < 7; nt++) {
        sacc[nt][0] *= inv0; sacc[nt][1] *= inv0;
        sacc[nt][2] *= inv1; sacc[nt][3] *= inv1;
    }

    float o[4][4];
#pragma unroll
    for (int dt = 0; dt < 4; dt++)
#pragma unroll
        for (int r = 0; r < 4; r++) o[dt][r] = 0.f;

#pragma unroll
    for (int kb = 0; kb < 4; kb++) {
        unsigned a[4];
        int n0 = 2 * kb, n1 = 2 * kb + 1;
        a[0] = pk(sacc[n0][0], sacc[n0][1]);
        a[1] = pk(sacc[n0][2], sacc[n0][3]);
        if (n1 < 7) {
            a[2] = pk(sacc[n1][0], sacc[n1][1]);
            a[3] = pk(sacc[n1][2], sacc[n1][3]);
        } else { a[2] = 0u; a[3] = 0u; }
#pragma unroll
        for (int dt = 0; dt < 4; dt++) {
            uint2 bv = *(const uint2*)(vt + (dt * 4 + kb) * 64 + lane * 2);
            mma_bf16(o[dt], a, (const unsigned*)&bv);
        }
    }

    int r0 = m0 + gid, r1 = r0 + 8;
    int R0 = w * NTOK + r0, R1 = w * NTOK + r1;
    unsigned* d0 = g_ca + (size_t)(R0 >> 7) * AT16;
    unsigned* d1 = g_ca + (size_t)(R1 >> 7) * AT16;
    int rr0 = R0 & 127, rr1 = R1 & 127;
#pragma unroll
    for (int dt = 0; dt < 4; dt++) {
        int p = (h * HDIM + dt * 8 + 2 * qid) >> 1;
        if (r0 < NTOK) d0[aw_idx(rr0, p)] = pk(o[dt][0], o[dt][1]);
        if (r1 < NTOK) d1[aw_idx(rr1, p)] = pk(o[dt][2], o[dt][3]);
    }
}

// ---------------- launch ----------------
extern "C" void kernel_launch(void* const* d_in, const int* in_sizes, int n_in,
                              void* d_out, int out_size)
{
    const float* inputs = (const float*)d_in[0];
    const float* amask  = (const float*)d_in[1];
    const float* n1g    = (const float*)d_in[2];
    const float* n1b    = (const float*)d_in[3];
    const float* qkvw   = (const float*)d_in[4];
    const float* qkvb   = (const float*)d_in[5];
    const float* rpt    = (const float*)d_in[6];
    const int*   rpi    = (const int*)d_in[7];
    const float* pw     = (const float*)d_in[8];
    const float* pb     = (const float*)d_in[9];
    const float* lw     = (const float*)d_in[10];
    const float* lb     = (const float*)d_in[11];
    float* out = (float*)d_out;

    bias2_kernel<<<(NHEAD * NWIN * BM_SZ + 255) / 256, 256>>>(rpt, rpi, amask);
    wswz_kernel<<<((576 + 192 + 192) * 96 + 255) / 256, 256>>>(qkvw, pw, lw);
    ln_kernel<<<TOK / 8, 256>>>(inputs, n1g, n1b);
    gemm_kernel<0><<<dim3(9, 784), 256>>>(qkvb, nullptr, nullptr);
    attn_kernel<<<dim3(BWIN, NHEAD), 128>>>();
    gemm_kernel<1><<<dim3(3, 784), 256>>>(pb, nullptr, nullptr);
    gemm_kernel<2><<<dim3(3, 784), 256>>>(lb, inputs, out);
}